// round 15
// baseline (speedup 1.0000x reference)
#include <cuda_runtime.h>
#include <cuda_fp16.h>

#define BB 32
#define NN 512
#define MM 32
#define HA 64
#define HB 101
#define NROWS (BB*NN*MM)      /* 524288 */
#define NNODES (BB*NN)        /* 16384  */
#define NKF 6
#define FDIM 229
#define HO 128

// -------- scratch (device globals; no allocation) --------
__device__ uint4  d_SGp[NROWS];                 // per-row: 6 gauss taps (half) + (c<<16|nb)
__device__ float  d_atom[NNODES*HA];            // node features
__device__ float  d_P[NNODES*HO];               // self projection (fp32)
__device__ __align__(16) __half d_Pnh[NNODES*HO];   // nbr projection (fp16)
__device__ __align__(16) __half d_Wh[4*HB*HO];      // fp16 W_emb, channel-quad interleaved
__device__ float  d_summed[NNODES*HA];
__device__ double g_s1[HO], g_q1[HO], g_s2[HA], g_q2[HA];

__device__ __forceinline__ unsigned h2_to_u(__half2 h) { unsigned u; *(__half2*)&u = h; return u; }
__device__ __forceinline__ __half2 u_to_h2(unsigned u) { __half2 h; *(unsigned*)&h = u; return h; }
__device__ __forceinline__ float sigt(float x) {
    float t; asm("tanh.approx.f32 %0,%1;" : "=f"(t) : "f"(x * 0.5f));
    return fmaf(t, 0.5f, 0.5f);
}

// -------- init atom = emb_w broadcast, zero stat accumulators --------
__global__ void k_init(const float* __restrict__ emb) {
    int i = blockIdx.x * 256 + threadIdx.x;
    int n = (i >> 6) & (NN - 1);
    d_atom[i] = emb[(n << 6) | (i & 63)];
    if (i < HO) { g_s1[i] = 0.0; g_q1[i] = 0.0; }
    if (i < HA) { g_s2[i] = 0.0; g_q2[i] = 0.0; }
}

// -------- fp16 W_emb, interleaved quads: (l, r, j) -> halves {2j,2j+1,64+2j,65+2j} --------
__global__ void k_wprep(const float* __restrict__ fcw) {
    int i = blockIdx.x * 256 + threadIdx.x;     // 202*256 = 51712 = 4*101*128
    int t = i & 3, j = (i >> 2) & 31, r = (i >> 7) % HB, l = i / (HB * HO);
    int chan = (t < 2) ? (2 * j + t) : (64 + 2 * j + (t - 2));
    d_Wh[i] = __float2half(fcw[l * FDIM * HO + (128 + r) * HO + chan]);
}

// -------- gaussian taps (half) + packed (c,nb), once per launch --------
__global__ void k_gauss(const float* __restrict__ dist, const int* __restrict__ adj) {
    int row = blockIdx.x * 256 + threadIdx.x;
    float r = dist[row] * 10.0f;
    int b0 = min(max(__float2int_rd(r) - 2, 0), 101 - NKF);
    float x0 = r - (float)b0;
    float g = __expf(-x0 * x0);
    float T = __expf(2.0f * x0 - 1.0f);
    const float E2[5] = {1.0f, 1.3533528e-1f, 1.8315639e-2f, 2.4787522e-3f, 3.3546263e-4f};
    float gs[NKF]; gs[0] = g;
#pragma unroll
    for (int k = 0; k < 5; k++) { g *= T * E2[k]; gs[k + 1] = g; }
    uint4 p;
    p.x = h2_to_u(__floats2half2_rn(gs[0], gs[1]));
    p.y = h2_to_u(__floats2half2_rn(gs[2], gs[3]));
    p.z = h2_to_u(__floats2half2_rn(gs[4], gs[5]));
    p.w = ((unsigned)b0 << 16) | (unsigned)adj[row];
    d_SGp[row] = p;
}

// -------- node projection (R7 geometry): half 0 -> d_P fp32, half 1 -> d_Pnh fp16 --------
__global__ void k_proj(const float* __restrict__ fcw, int layer) {
    __shared__ float At[64][68];
    __shared__ float Ws[32][128];
    int tid = threadIdx.x;
    int node0 = blockIdx.x * 64;
    int half = blockIdx.y;
    if (blockIdx.x == 0 && half == 0 && tid < HA) { g_s2[tid] = 0.0; g_q2[tid] = 0.0; }
    for (int i = tid; i < 64 * 64; i += 256) {
        int n = i >> 6, k = i & 63;
        At[k][n] = d_atom[(node0 + n) * 64 + k];
    }
    int tx = tid & 15, ty = tid >> 4;
    float acc[4][8];
#pragma unroll
    for (int r = 0; r < 4; r++)
#pragma unroll
        for (int c = 0; c < 8; c++) acc[r][c] = 0.f;
    const float* Wg = fcw + layer * FDIM * HO + half * 64 * HO;
    for (int chunk = 0; chunk < 2; chunk++) {
        __syncthreads();
        for (int i = tid; i < 32 * 128; i += 256) Ws[i >> 7][i & 127] = Wg[chunk * 4096 + i];
        __syncthreads();
#pragma unroll 8
        for (int k = 0; k < 32; k++) {
            float4 a = *(const float4*)&At[chunk * 32 + k][ty * 4];
            float4 w0 = *(const float4*)&Ws[k][tx * 8];
            float4 w1 = *(const float4*)&Ws[k][tx * 8 + 4];
            float av[4] = {a.x, a.y, a.z, a.w};
            float wv[8] = {w0.x, w0.y, w0.z, w0.w, w1.x, w1.y, w1.z, w1.w};
#pragma unroll
            for (int r = 0; r < 4; r++)
#pragma unroll
                for (int c = 0; c < 8; c++) acc[r][c] += av[r] * wv[c];
        }
    }
    if (half == 0) {
#pragma unroll
        for (int r = 0; r < 4; r++) {
            float* op = d_P + (size_t)(node0 + ty * 4 + r) * HO + tx * 8;
            *(float4*)op = make_float4(acc[r][0], acc[r][1], acc[r][2], acc[r][3]);
            *(float4*)(op + 4) = make_float4(acc[r][4], acc[r][5], acc[r][6], acc[r][7]);
        }
    } else {
#pragma unroll
        for (int r = 0; r < 4; r++) {
            __half2* op = (__half2*)(d_Pnh + (size_t)(node0 + ty * 4 + r) * HO + tx * 8);
            op[0] = __floats2half2_rn(acc[r][0], acc[r][1]);
            op[1] = __floats2half2_rn(acc[r][2], acc[r][3]);
            op[2] = __floats2half2_rn(acc[r][4], acc[r][5]);
            op[3] = __floats2half2_rn(acc[r][6], acc[r][7]);
        }
    }
}

// shared inner step: compute gated half2 pair for row m of this node
#define GATED_STEP(m)                                                                  \
    unsigned uw = __shfl_sync(0xffffffffu, p.w, m);                                    \
    unsigned u0 = __shfl_sync(0xffffffffu, p.x, m);                                    \
    unsigned u1 = __shfl_sync(0xffffffffu, p.y, m);                                    \
    unsigned u2 = __shfl_sync(0xffffffffu, p.z, m);                                    \
    int c = uw >> 16, nb = uw & 0xffff;                                                \
    __half2 g01 = u_to_h2(u0), g23 = u_to_h2(u1), g45 = u_to_h2(u2);                   \
    const __half* wp = Wsh + c * HO + lane * 4;                                        \
    uint2 w0 = *(const uint2*)(wp);                                                    \
    uint2 w1 = *(const uint2*)(wp + HO);                                               \
    uint2 w2 = *(const uint2*)(wp + 2 * HO);                                           \
    uint2 w3 = *(const uint2*)(wp + 3 * HO);                                           \
    uint2 w4 = *(const uint2*)(wp + 4 * HO);                                           \
    uint2 w5 = *(const uint2*)(wp + 5 * HO);                                           \
    __half2 accf = __hmul2(__half2half2(__low2half(g01)), u_to_h2(w0.x));              \
    __half2 accc = __hmul2(__half2half2(__low2half(g01)), u_to_h2(w0.y));              \
    accf = __hfma2(__half2half2(__high2half(g01)), u_to_h2(w1.x), accf);               \
    accc = __hfma2(__half2half2(__high2half(g01)), u_to_h2(w1.y), accc);               \
    accf = __hfma2(__half2half2(__low2half(g23)),  u_to_h2(w2.x), accf);               \
    accc = __hfma2(__half2half2(__low2half(g23)),  u_to_h2(w2.y), accc);               \
    accf = __hfma2(__half2half2(__high2half(g23)), u_to_h2(w3.x), accf);               \
    accc = __hfma2(__half2half2(__high2half(g23)), u_to_h2(w3.y), accc);               \
    accf = __hfma2(__half2half2(__low2half(g45)),  u_to_h2(w4.x), accf);               \
    accc = __hfma2(__half2half2(__low2half(g45)),  u_to_h2(w4.y), accc);               \
    accf = __hfma2(__half2half2(__high2half(g45)), u_to_h2(w5.x), accf);               \
    accc = __hfma2(__half2half2(__high2half(g45)), u_to_h2(w5.y), accc);               \
    const __half* pn = Pn + nb * HO + ch;                                              \
    accf = __hadd2(accf, *(const __half2*)(pn));                                       \
    accc = __hadd2(accc, *(const __half2*)(pn + 64));                                  \
    float2 vf = __half22float2(accf), vc = __half22float2(accc);                       \
    vf.x += base0.x; vf.y += base0.y; vc.x += base1.x; vc.y += base1.y;

// -------- pass 1: gated recompute for BN1 stats only --------
__global__ void __launch_bounds__(256, 6) k_gstats(const float* __restrict__ fcb, int layer) {
    __shared__ __align__(16) __half Wsh[HB * HO];
    __shared__ float bs[HO], bq[HO];
    int tid = threadIdx.x, warp = tid >> 5, lane = tid & 31;
    const uint4* Wg = (const uint4*)(d_Wh + layer * HB * HO);
    for (int i = tid; i < HB * HO / 8; i += 256) ((uint4*)Wsh)[i] = Wg[i];
    if (tid < HO) { bs[tid] = 0.f; bq[tid] = 0.f; }
    __syncthreads();

    int node = blockIdx.x * 8 + warp;
    uint4 p = d_SGp[node * MM + lane];
    int ch = 2 * lane;
    float2 base0 = *(const float2*)(d_P + node * HO + ch);
    float2 base1 = *(const float2*)(d_P + node * HO + 64 + ch);
    float2 bb0 = *(const float2*)(fcb + layer * HO + ch);
    float2 bb1 = *(const float2*)(fcb + layer * HO + 64 + ch);
    base0.x += bb0.x; base0.y += bb0.y; base1.x += bb1.x; base1.y += bb1.y;
    const __half* Pn = d_Pnh + (size_t)(node & ~(NN - 1)) * HO;

    float2 s0 = make_float2(0, 0), s1 = make_float2(0, 0);
    float2 q0 = make_float2(0, 0), q1 = make_float2(0, 0);
    for (int m = 0; m < MM; m++) {
        GATED_STEP(m)
        s0.x += vf.x; s0.y += vf.y; s1.x += vc.x; s1.y += vc.y;
        q0.x += vf.x * vf.x; q0.y += vf.y * vf.y;
        q1.x += vc.x * vc.x; q1.y += vc.y * vc.y;
    }
    atomicAdd(&bs[ch], s0.x);      atomicAdd(&bs[ch + 1], s0.y);
    atomicAdd(&bs[ch + 64], s1.x); atomicAdd(&bs[ch + 65], s1.y);
    atomicAdd(&bq[ch], q0.x);      atomicAdd(&bq[ch + 1], q0.y);
    atomicAdd(&bq[ch + 64], q1.x); atomicAdd(&bq[ch + 65], q1.y);
    __syncthreads();
    if (tid < HO) { atomicAdd(&g_s1[tid], (double)bs[tid]); atomicAdd(&g_q1[tid], (double)bq[tid]); }
}

// -------- pass 2: recompute gated, BN1 apply, tanh-sigmoid*relu, sum_m, BN2 stats --------
__global__ void __launch_bounds__(256, 5) k_greduce(const float* __restrict__ fcb,
                          const float* __restrict__ g1, const float* __restrict__ b1, int layer) {
    __shared__ __align__(16) __half Wsh[HB * HO];
    __shared__ float s_sc[HO], s_sh[HO];
    __shared__ float bs[HA], bq[HA];
    int tid = threadIdx.x, warp = tid >> 5, lane = tid & 31;
    const uint4* Wg = (const uint4*)(d_Wh + layer * HB * HO);
    for (int i = tid; i < HB * HO / 8; i += 256) ((uint4*)Wsh)[i] = Wg[i];
    if (tid < HO) {
        double inv = 1.0 / (double)NROWS;
        double mean = g_s1[tid] * inv;
        double var = g_q1[tid] * inv - mean * mean;
        float sc = g1[layer * HO + tid] * (float)(1.0 / sqrt(var + 1e-5));
        s_sc[tid] = sc;
        s_sh[tid] = b1[layer * HO + tid] - (float)mean * sc;
    }
    if (tid < HA) { bs[tid] = 0.f; bq[tid] = 0.f; }
    __syncthreads();

    int node = blockIdx.x * 8 + warp;
    uint4 p = d_SGp[node * MM + lane];
    int ch = 2 * lane;
    float2 base0 = *(const float2*)(d_P + node * HO + ch);
    float2 base1 = *(const float2*)(d_P + node * HO + 64 + ch);
    float2 bb0 = *(const float2*)(fcb + layer * HO + ch);
    float2 bb1 = *(const float2*)(fcb + layer * HO + 64 + ch);
    base0.x += bb0.x; base0.y += bb0.y; base1.x += bb1.x; base1.y += bb1.y;
    float sc0x = s_sc[ch], sc0y = s_sc[ch + 1], sh0x = s_sh[ch], sh0y = s_sh[ch + 1];
    float sc1x = s_sc[ch + 64], sc1y = s_sc[ch + 65], sh1x = s_sh[ch + 64], sh1y = s_sh[ch + 65];
    const __half* Pn = d_Pnh + (size_t)(node & ~(NN - 1)) * HO;

    float outx = 0.f, outy = 0.f;
    for (int m = 0; m < MM; m++) {
        GATED_STEP(m)
        float fx = vf.x * sc0x + sh0x;
        float fy = vf.y * sc0y + sh0y;
        float cx = vc.x * sc1x + sh1x;
        float cy = vc.y * sc1y + sh1y;
        outx += fmaxf(cx, 0.f) * sigt(fx);
        outy += fmaxf(cy, 0.f) * sigt(fy);
    }
    *(float2*)(d_summed + node * HA + ch) = make_float2(outx, outy);
    atomicAdd(&bs[ch], outx);            atomicAdd(&bs[ch + 1], outy);
    atomicAdd(&bq[ch], outx * outx);     atomicAdd(&bq[ch + 1], outy * outy);
    __syncthreads();
    if (tid < HA) { atomicAdd(&g_s2[tid], (double)bs[tid]); atomicAdd(&g_q2[tid], (double)bq[tid]); }
}

// -------- residual + relu, with inline BN2 finalize --------
__global__ void k_update(const float* __restrict__ g2, const float* __restrict__ b2, int layer) {
    __shared__ float sc2[HA], sh2[HA];
    int tid = threadIdx.x;
    if (tid < HA) {
        double inv = 1.0 / (double)NNODES;
        double mean = g_s2[tid] * inv;
        double var = g_q2[tid] * inv - mean * mean;
        float sc = g2[layer * HA + tid] * (float)(1.0 / sqrt(var + 1e-5));
        sc2[tid] = sc;
        sh2[tid] = b2[layer * HA + tid] - (float)mean * sc;
    }
    if (blockIdx.x == 0 && tid < HO) { g_s1[tid] = 0.0; g_q1[tid] = 0.0; }
    __syncthreads();
    int i = blockIdx.x * 256 + tid;
    int ch = i & 63;
    float v = d_atom[i] + d_summed[i] * sc2[ch] + sh2[ch];
    d_atom[i] = fmaxf(v, 0.f);
}

// -------- pool, classify, softmax --------
__global__ void k_final(const float* __restrict__ clsw, const float* __restrict__ clsb,
                        float* __restrict__ out) {
    __shared__ float red[256];
    __shared__ float pooled[HA];
    __shared__ float lg[10], ex[10];
    __shared__ float mx, isum;
    int b = blockIdx.x, tid = threadIdx.x;
    int ch = tid & 63, seg = tid >> 6;
    const float* ab = d_atom + b * NN * HA;
    float acc = 0.f;
    for (int n = seg; n < NN; n += 4) acc += fmaxf(ab[n * HA + ch], 0.f);
    red[tid] = acc;
    __syncthreads();
    if (tid < HA) pooled[tid] = (red[tid] + red[tid + 64] + red[tid + 128] + red[tid + 192]) * (1.0f / (float)NN);
    __syncthreads();
    if (tid < 10) {
        float a = clsb[tid];
#pragma unroll
        for (int k = 0; k < HA; k++) a += pooled[k] * clsw[k * 10 + tid];
        lg[tid] = a;
    }
    __syncthreads();
    if (tid == 0) { float m = lg[0]; for (int i = 1; i < 10; i++) m = fmaxf(m, lg[i]); mx = m; }
    __syncthreads();
    if (tid < 10) ex[tid] = expf(lg[tid] - mx);
    __syncthreads();
    if (tid == 0) { float s = 0.f; for (int i = 0; i < 10; i++) s += ex[i]; isum = 1.f / s; }
    __syncthreads();
    if (tid < 10) out[b * 10 + tid] = ex[tid] * isum;
}

extern "C" void kernel_launch(void* const* d_in, const int* in_sizes, int n_in,
                              void* d_out, int out_size) {
    const float* dist = (const float*)d_in[0];
    const int*   adj  = (const int*)d_in[1];
    const float* emb  = (const float*)d_in[2];
    const float* fcw  = (const float*)d_in[3];
    const float* fcb  = (const float*)d_in[4];
    const float* b1g  = (const float*)d_in[5];
    const float* b1b  = (const float*)d_in[6];
    const float* b2g  = (const float*)d_in[7];
    const float* b2b  = (const float*)d_in[8];
    const float* clsw = (const float*)d_in[9];
    const float* clsb = (const float*)d_in[10];
    float* out = (float*)d_out;

    k_init<<<NNODES * HA / 256, 256>>>(emb);
    k_wprep<<<202, 256>>>(fcw);
    k_gauss<<<NROWS / 256, 256>>>(dist, adj);
    for (int l = 0; l < 4; l++) {
        k_proj<<<dim3(NNODES / 64, 2), 256>>>(fcw, l);
        k_gstats<<<NNODES / 8, 256>>>(fcb, l);
        k_greduce<<<NNODES / 8, 256>>>(fcb, b1g, b1b, l);
        k_update<<<NNODES * HA / 256, 256>>>(b2g, b2b, l);
    }
    k_final<<<BB, 256>>>(clsw, clsb, out);
}

// round 16
// speedup vs baseline: 1.0448x; 1.0448x over previous
#include <cuda_runtime.h>
#include <cuda_fp16.h>

#define BB 32
#define NN 512
#define MM 32
#define HA 64
#define HB 101
#define NROWS (BB*NN*MM)      /* 524288 */
#define NNODES (BB*NN)        /* 16384  */
#define NKF 6
#define FDIM 229
#define HO 128

// -------- scratch (device globals; no allocation) --------
__device__ uint4  d_SGp[NROWS];                 // per-row: 6 gauss taps (half) + (c<<16|nb)
__device__ float  d_atom[NNODES*HA];            // node features
__device__ float  d_P[NNODES*HO];               // self projection (fp32)
__device__ __align__(16) __half d_Pnh[NNODES*HO];   // nbr projection (fp16)
__device__ __align__(16) __half d_Wh[4*HB*HO];      // fp16 W_emb, channel-quad interleaved
__device__ float  d_summed[NNODES*HA];
__device__ double g_s1[HO], g_q1[HO], g_s2[HA], g_q2[HA];

__device__ __forceinline__ unsigned h2_to_u(__half2 h) { unsigned u; *(__half2*)&u = h; return u; }
__device__ __forceinline__ __half2 u_to_h2(unsigned u) { __half2 h; *(unsigned*)&h = u; return h; }
__device__ __forceinline__ float sigt(float x) {
    float t; asm("tanh.approx.f32 %0,%1;" : "=f"(t) : "f"(x * 0.5f));
    return fmaf(t, 0.5f, 0.5f);
}

// -------- init atom = emb_w broadcast, zero stat accumulators --------
__global__ void k_init(const float* __restrict__ emb) {
    int i = blockIdx.x * 256 + threadIdx.x;
    int n = (i >> 6) & (NN - 1);
    d_atom[i] = emb[(n << 6) | (i & 63)];
    if (i < HO) { g_s1[i] = 0.0; g_q1[i] = 0.0; }
    if (i < HA) { g_s2[i] = 0.0; g_q2[i] = 0.0; }
}

// -------- fp16 W_emb, interleaved quads: (l, r, j) -> halves {2j,2j+1,64+2j,65+2j} --------
__global__ void k_wprep(const float* __restrict__ fcw) {
    int i = blockIdx.x * 256 + threadIdx.x;     // 202*256 = 51712 = 4*101*128
    int t = i & 3, j = (i >> 2) & 31, r = (i >> 7) % HB, l = i / (HB * HO);
    int chan = (t < 2) ? (2 * j + t) : (64 + 2 * j + (t - 2));
    d_Wh[i] = __float2half(fcw[l * FDIM * HO + (128 + r) * HO + chan]);
}

// -------- gaussian taps (half) + packed (c,nb), once per launch --------
__global__ void k_gauss(const float* __restrict__ dist, const int* __restrict__ adj) {
    int row = blockIdx.x * 256 + threadIdx.x;
    float r = dist[row] * 10.0f;
    int b0 = min(max(__float2int_rd(r) - 2, 0), 101 - NKF);
    float x0 = r - (float)b0;
    float g = __expf(-x0 * x0);
    float T = __expf(2.0f * x0 - 1.0f);
    const float E2[5] = {1.0f, 1.3533528e-1f, 1.8315639e-2f, 2.4787522e-3f, 3.3546263e-4f};
    float gs[NKF]; gs[0] = g;
#pragma unroll
    for (int k = 0; k < 5; k++) { g *= T * E2[k]; gs[k + 1] = g; }
    uint4 p;
    p.x = h2_to_u(__floats2half2_rn(gs[0], gs[1]));
    p.y = h2_to_u(__floats2half2_rn(gs[2], gs[3]));
    p.z = h2_to_u(__floats2half2_rn(gs[4], gs[5]));
    p.w = ((unsigned)b0 << 16) | (unsigned)adj[row];
    d_SGp[row] = p;
}

// -------- node projection (R7 geometry): half 0 -> d_P fp32, half 1 -> d_Pnh fp16 --------
__global__ void k_proj(const float* __restrict__ fcw, int layer) {
    __shared__ float At[64][68];
    __shared__ float Ws[32][128];
    int tid = threadIdx.x;
    int node0 = blockIdx.x * 64;
    int half = blockIdx.y;
    if (blockIdx.x == 0 && half == 0 && tid < HA) { g_s2[tid] = 0.0; g_q2[tid] = 0.0; }
    for (int i = tid; i < 64 * 64; i += 256) {
        int n = i >> 6, k = i & 63;
        At[k][n] = d_atom[(node0 + n) * 64 + k];
    }
    int tx = tid & 15, ty = tid >> 4;
    float acc[4][8];
#pragma unroll
    for (int r = 0; r < 4; r++)
#pragma unroll
        for (int c = 0; c < 8; c++) acc[r][c] = 0.f;
    const float* Wg = fcw + layer * FDIM * HO + half * 64 * HO;
    for (int chunk = 0; chunk < 2; chunk++) {
        __syncthreads();
        for (int i = tid; i < 32 * 128; i += 256) Ws[i >> 7][i & 127] = Wg[chunk * 4096 + i];
        __syncthreads();
#pragma unroll 8
        for (int k = 0; k < 32; k++) {
            float4 a = *(const float4*)&At[chunk * 32 + k][ty * 4];
            float4 w0 = *(const float4*)&Ws[k][tx * 8];
            float4 w1 = *(const float4*)&Ws[k][tx * 8 + 4];
            float av[4] = {a.x, a.y, a.z, a.w};
            float wv[8] = {w0.x, w0.y, w0.z, w0.w, w1.x, w1.y, w1.z, w1.w};
#pragma unroll
            for (int r = 0; r < 4; r++)
#pragma unroll
                for (int c = 0; c < 8; c++) acc[r][c] += av[r] * wv[c];
        }
    }
    if (half == 0) {
#pragma unroll
        for (int r = 0; r < 4; r++) {
            float* op = d_P + (size_t)(node0 + ty * 4 + r) * HO + tx * 8;
            *(float4*)op = make_float4(acc[r][0], acc[r][1], acc[r][2], acc[r][3]);
            *(float4*)(op + 4) = make_float4(acc[r][4], acc[r][5], acc[r][6], acc[r][7]);
        }
    } else {
#pragma unroll
        for (int r = 0; r < 4; r++) {
            __half2* op = (__half2*)(d_Pnh + (size_t)(node0 + ty * 4 + r) * HO + tx * 8);
            op[0] = __floats2half2_rn(acc[r][0], acc[r][1]);
            op[1] = __floats2half2_rn(acc[r][2], acc[r][3]);
            op[2] = __floats2half2_rn(acc[r][4], acc[r][5]);
            op[3] = __floats2half2_rn(acc[r][6], acc[r][7]);
        }
    }
}

// shared inner step: compute gated half2 pair for row m of this node
#define GATED_STEP(m)                                                                  \
    unsigned uw = __shfl_sync(0xffffffffu, p.w, m);                                    \
    unsigned u0 = __shfl_sync(0xffffffffu, p.x, m);                                    \
    unsigned u1 = __shfl_sync(0xffffffffu, p.y, m);                                    \
    unsigned u2 = __shfl_sync(0xffffffffu, p.z, m);                                    \
    int c = uw >> 16, nb = uw & 0xffff;                                                \
    __half2 g01 = u_to_h2(u0), g23 = u_to_h2(u1), g45 = u_to_h2(u2);                   \
    const __half* wp = Wsh + c * HO + lane * 4;                                        \
    uint2 w0 = *(const uint2*)(wp);                                                    \
    uint2 w1 = *(const uint2*)(wp + HO);                                               \
    uint2 w2 = *(const uint2*)(wp + 2 * HO);                                           \
    uint2 w3 = *(const uint2*)(wp + 3 * HO);                                           \
    uint2 w4 = *(const uint2*)(wp + 4 * HO);                                           \
    uint2 w5 = *(const uint2*)(wp + 5 * HO);                                           \
    __half2 accf = __hmul2(__half2half2(__low2half(g01)), u_to_h2(w0.x));              \
    __half2 accc = __hmul2(__half2half2(__low2half(g01)), u_to_h2(w0.y));              \
    accf = __hfma2(__half2half2(__high2half(g01)), u_to_h2(w1.x), accf);               \
    accc = __hfma2(__half2half2(__high2half(g01)), u_to_h2(w1.y), accc);               \
    accf = __hfma2(__half2half2(__low2half(g23)),  u_to_h2(w2.x), accf);               \
    accc = __hfma2(__half2half2(__low2half(g23)),  u_to_h2(w2.y), accc);               \
    accf = __hfma2(__half2half2(__high2half(g23)), u_to_h2(w3.x), accf);               \
    accc = __hfma2(__half2half2(__high2half(g23)), u_to_h2(w3.y), accc);               \
    accf = __hfma2(__half2half2(__low2half(g45)),  u_to_h2(w4.x), accf);               \
    accc = __hfma2(__half2half2(__low2half(g45)),  u_to_h2(w4.y), accc);               \
    accf = __hfma2(__half2half2(__high2half(g45)), u_to_h2(w5.x), accf);               \
    accc = __hfma2(__half2half2(__high2half(g45)), u_to_h2(w5.y), accc);               \
    const __half* pn = Pn + nb * HO + ch;                                              \
    accf = __hadd2(accf, *(const __half2*)(pn));                                       \
    accc = __hadd2(accc, *(const __half2*)(pn + 64));                                  \
    float2 vf = __half22float2(accf), vc = __half22float2(accc);                       \
    vf.x += base0.x; vf.y += base0.y; vc.x += base1.x; vc.y += base1.y;

// -------- pass 1: gated recompute for BN1 stats only --------
__global__ void __launch_bounds__(256, 5) k_gstats(const float* __restrict__ fcb, int layer) {
    __shared__ __align__(16) __half Wsh[HB * HO];
    __shared__ float bs[HO], bq[HO];
    int tid = threadIdx.x, warp = tid >> 5, lane = tid & 31;
    const uint4* Wg = (const uint4*)(d_Wh + layer * HB * HO);
    for (int i = tid; i < HB * HO / 8; i += 256) ((uint4*)Wsh)[i] = Wg[i];
    if (tid < HO) { bs[tid] = 0.f; bq[tid] = 0.f; }
    __syncthreads();

    int node = blockIdx.x * 8 + warp;
    uint4 p = d_SGp[node * MM + lane];
    int ch = 2 * lane;
    float2 base0 = *(const float2*)(d_P + node * HO + ch);
    float2 base1 = *(const float2*)(d_P + node * HO + 64 + ch);
    float2 bb0 = *(const float2*)(fcb + layer * HO + ch);
    float2 bb1 = *(const float2*)(fcb + layer * HO + 64 + ch);
    base0.x += bb0.x; base0.y += bb0.y; base1.x += bb1.x; base1.y += bb1.y;
    const __half* Pn = d_Pnh + (size_t)(node & ~(NN - 1)) * HO;

    float2 s0 = make_float2(0, 0), s1 = make_float2(0, 0);
    float2 q0 = make_float2(0, 0), q1 = make_float2(0, 0);
    for (int m = 0; m < MM; m++) {
        GATED_STEP(m)
        s0.x += vf.x; s0.y += vf.y; s1.x += vc.x; s1.y += vc.y;
        q0.x += vf.x * vf.x; q0.y += vf.y * vf.y;
        q1.x += vc.x * vc.x; q1.y += vc.y * vc.y;
    }
    atomicAdd(&bs[ch], s0.x);      atomicAdd(&bs[ch + 1], s0.y);
    atomicAdd(&bs[ch + 64], s1.x); atomicAdd(&bs[ch + 65], s1.y);
    atomicAdd(&bq[ch], q0.x);      atomicAdd(&bq[ch + 1], q0.y);
    atomicAdd(&bq[ch + 64], q1.x); atomicAdd(&bq[ch + 65], q1.y);
    __syncthreads();
    if (tid < HO) { atomicAdd(&g_s1[tid], (double)bs[tid]); atomicAdd(&g_q1[tid], (double)bq[tid]); }
}

// -------- pass 2: recompute gated, BN1 apply, tanh-sigmoid*relu, sum_m, BN2 stats --------
__global__ void __launch_bounds__(256, 5) k_greduce(const float* __restrict__ fcb,
                          const float* __restrict__ g1, const float* __restrict__ b1, int layer) {
    __shared__ __align__(16) __half Wsh[HB * HO];
    __shared__ float s_sc[HO], s_sh[HO];
    __shared__ float bs[HA], bq[HA];
    int tid = threadIdx.x, warp = tid >> 5, lane = tid & 31;
    const uint4* Wg = (const uint4*)(d_Wh + layer * HB * HO);
    for (int i = tid; i < HB * HO / 8; i += 256) ((uint4*)Wsh)[i] = Wg[i];
    if (tid < HO) {
        double inv = 1.0 / (double)NROWS;
        double mean = g_s1[tid] * inv;
        double var = g_q1[tid] * inv - mean * mean;
        float sc = g1[layer * HO + tid] * (float)(1.0 / sqrt(var + 1e-5));
        s_sc[tid] = sc;
        s_sh[tid] = b1[layer * HO + tid] - (float)mean * sc;
    }
    if (tid < HA) { bs[tid] = 0.f; bq[tid] = 0.f; }
    __syncthreads();

    int node = blockIdx.x * 8 + warp;
    uint4 p = d_SGp[node * MM + lane];
    int ch = 2 * lane;
    float2 base0 = *(const float2*)(d_P + node * HO + ch);
    float2 base1 = *(const float2*)(d_P + node * HO + 64 + ch);
    float2 bb0 = *(const float2*)(fcb + layer * HO + ch);
    float2 bb1 = *(const float2*)(fcb + layer * HO + 64 + ch);
    base0.x += bb0.x; base0.y += bb0.y; base1.x += bb1.x; base1.y += bb1.y;
    float sc0x = s_sc[ch], sc0y = s_sc[ch + 1], sh0x = s_sh[ch], sh0y = s_sh[ch + 1];
    float sc1x = s_sc[ch + 64], sc1y = s_sc[ch + 65], sh1x = s_sh[ch + 64], sh1y = s_sh[ch + 65];
    const __half* Pn = d_Pnh + (size_t)(node & ~(NN - 1)) * HO;

    float outx = 0.f, outy = 0.f;
    for (int m = 0; m < MM; m++) {
        GATED_STEP(m)
        float fx = vf.x * sc0x + sh0x;
        float fy = vf.y * sc0y + sh0y;
        float cx = vc.x * sc1x + sh1x;
        float cy = vc.y * sc1y + sh1y;
        outx += fmaxf(cx, 0.f) * sigt(fx);
        outy += fmaxf(cy, 0.f) * sigt(fy);
    }
    *(float2*)(d_summed + node * HA + ch) = make_float2(outx, outy);
    atomicAdd(&bs[ch], outx);            atomicAdd(&bs[ch + 1], outy);
    atomicAdd(&bq[ch], outx * outx);     atomicAdd(&bq[ch + 1], outy * outy);
    __syncthreads();
    if (tid < HA) { atomicAdd(&g_s2[tid], (double)bs[tid]); atomicAdd(&g_q2[tid], (double)bq[tid]); }
}

// -------- residual + relu, with inline BN2 finalize --------
__global__ void k_update(const float* __restrict__ g2, const float* __restrict__ b2, int layer) {
    __shared__ float sc2[HA], sh2[HA];
    int tid = threadIdx.x;
    if (tid < HA) {
        double inv = 1.0 / (double)NNODES;
        double mean = g_s2[tid] * inv;
        double var = g_q2[tid] * inv - mean * mean;
        float sc = g2[layer * HA + tid] * (float)(1.0 / sqrt(var + 1e-5));
        sc2[tid] = sc;
        sh2[tid] = b2[layer * HA + tid] - (float)mean * sc;
    }
    if (blockIdx.x == 0 && tid < HO) { g_s1[tid] = 0.0; g_q1[tid] = 0.0; }
    __syncthreads();
    int i = blockIdx.x * 256 + tid;
    int ch = i & 63;
    float v = d_atom[i] + d_summed[i] * sc2[ch] + sh2[ch];
    d_atom[i] = fmaxf(v, 0.f);
}

// -------- pool, classify, softmax --------
__global__ void k_final(const float* __restrict__ clsw, const float* __restrict__ clsb,
                        float* __restrict__ out) {
    __shared__ float red[256];
    __shared__ float pooled[HA];
    __shared__ float lg[10], ex[10];
    __shared__ float mx, isum;
    int b = blockIdx.x, tid = threadIdx.x;
    int ch = tid & 63, seg = tid >> 6;
    const float* ab = d_atom + b * NN * HA;
    float acc = 0.f;
    for (int n = seg; n < NN; n += 4) acc += fmaxf(ab[n * HA + ch], 0.f);
    red[tid] = acc;
    __syncthreads();
    if (tid < HA) pooled[tid] = (red[tid] + red[tid + 64] + red[tid + 128] + red[tid + 192]) * (1.0f / (float)NN);
    __syncthreads();
    if (tid < 10) {
        float a = clsb[tid];
#pragma unroll
        for (int k = 0; k < HA; k++) a += pooled[k] * clsw[k * 10 + tid];
        lg[tid] = a;
    }
    __syncthreads();
    if (tid == 0) { float m = lg[0]; for (int i = 1; i < 10; i++) m = fmaxf(m, lg[i]); mx = m; }
    __syncthreads();
    if (tid < 10) ex[tid] = expf(lg[tid] - mx);
    __syncthreads();
    if (tid == 0) { float s = 0.f; for (int i = 0; i < 10; i++) s += ex[i]; isum = 1.f / s; }
    __syncthreads();
    if (tid < 10) out[b * 10 + tid] = ex[tid] * isum;
}

extern "C" void kernel_launch(void* const* d_in, const int* in_sizes, int n_in,
                              void* d_out, int out_size) {
    const float* dist = (const float*)d_in[0];
    const int*   adj  = (const int*)d_in[1];
    const float* emb  = (const float*)d_in[2];
    const float* fcw  = (const float*)d_in[3];
    const float* fcb  = (const float*)d_in[4];
    const float* b1g  = (const float*)d_in[5];
    const float* b1b  = (const float*)d_in[6];
    const float* b2g  = (const float*)d_in[7];
    const float* b2b  = (const float*)d_in[8];
    const float* clsw = (const float*)d_in[9];
    const float* clsb = (const float*)d_in[10];
    float* out = (float*)d_out;

    k_init<<<NNODES * HA / 256, 256>>>(emb);
    k_wprep<<<202, 256>>>(fcw);
    k_gauss<<<NROWS / 256, 256>>>(dist, adj);
    for (int l = 0; l < 4; l++) {
        k_proj<<<dim3(NNODES / 64, 2), 256>>>(fcw, l);
        k_gstats<<<NNODES / 8, 256>>>(fcb, l);
        k_greduce<<<NNODES / 8, 256>>>(fcb, b1g, b1b, l);
        k_update<<<NNODES * HA / 256, 256>>>(b2g, b2b, l);
    }
    k_final<<<BB, 256>>>(clsw, clsb, out);
}

// round 17
// speedup vs baseline: 1.0648x; 1.0192x over previous
#include <cuda_runtime.h>
#include <cuda_fp16.h>

#define BB 32
#define NN 512
#define MM 32
#define HA 64
#define HB 101
#define NROWS (BB*NN*MM)      /* 524288 */
#define NNODES (BB*NN)        /* 16384  */
#define NKF 6
#define FDIM 229
#define HO 128

// -------- scratch (device globals; no allocation) --------
__device__ uint4  d_SGp[NROWS];                 // per-row: 6 gauss taps (half) + (c<<16|nb)
__device__ float  d_atom[NNODES*HA];            // node features
__device__ float  d_P[NNODES*HO];               // self projection (fp32)
__device__ __align__(16) __half d_Pnh[NNODES*HO];   // nbr projection (fp16)
__device__ __align__(16) __half d_Wh[4*HB*HO];      // fp16 W_emb, channel-quad interleaved
__device__ float  d_summed[NNODES*HA];
__device__ double g_s1[HO], g_q1[HO], g_s2[HA], g_q2[HA];

__device__ __forceinline__ unsigned h2_to_u(__half2 h) { unsigned u; *(__half2*)&u = h; return u; }
__device__ __forceinline__ __half2 u_to_h2(unsigned u) { __half2 h; *(unsigned*)&h = u; return h; }
__device__ __forceinline__ float sigt(float x) {
    float t; asm("tanh.approx.f32 %0,%1;" : "=f"(t) : "f"(x * 0.5f));
    return fmaf(t, 0.5f, 0.5f);
}

// -------- init atom = emb_w broadcast, zero stat accumulators --------
__global__ void k_init(const float* __restrict__ emb) {
    int i = blockIdx.x * 256 + threadIdx.x;
    int n = (i >> 6) & (NN - 1);
    d_atom[i] = emb[(n << 6) | (i & 63)];
    if (i < HO) { g_s1[i] = 0.0; g_q1[i] = 0.0; }
    if (i < HA) { g_s2[i] = 0.0; g_q2[i] = 0.0; }
}

// -------- fp16 W_emb, interleaved quads: (l, r, j) -> halves {2j,2j+1,64+2j,65+2j} --------
__global__ void k_wprep(const float* __restrict__ fcw) {
    int i = blockIdx.x * 256 + threadIdx.x;     // 202*256 = 51712 = 4*101*128
    int t = i & 3, j = (i >> 2) & 31, r = (i >> 7) % HB, l = i / (HB * HO);
    int chan = (t < 2) ? (2 * j + t) : (64 + 2 * j + (t - 2));
    d_Wh[i] = __float2half(fcw[l * FDIM * HO + (128 + r) * HO + chan]);
}

// -------- gaussian taps (half) + packed (c,nb), once per launch --------
__global__ void k_gauss(const float* __restrict__ dist, const int* __restrict__ adj) {
    int row = blockIdx.x * 256 + threadIdx.x;
    float r = dist[row] * 10.0f;
    int b0 = min(max(__float2int_rd(r) - 2, 0), 101 - NKF);
    float x0 = r - (float)b0;
    float g = __expf(-x0 * x0);
    float T = __expf(2.0f * x0 - 1.0f);
    const float E2[5] = {1.0f, 1.3533528e-1f, 1.8315639e-2f, 2.4787522e-3f, 3.3546263e-4f};
    float gs[NKF]; gs[0] = g;
#pragma unroll
    for (int k = 0; k < 5; k++) { g *= T * E2[k]; gs[k + 1] = g; }
    uint4 p;
    p.x = h2_to_u(__floats2half2_rn(gs[0], gs[1]));
    p.y = h2_to_u(__floats2half2_rn(gs[2], gs[3]));
    p.z = h2_to_u(__floats2half2_rn(gs[4], gs[5]));
    p.w = ((unsigned)b0 << 16) | (unsigned)adj[row];
    d_SGp[row] = p;
}

// -------- node projection, fused halves: At staged once; half0->d_P, half1->d_Pnh --------
__global__ void k_proj(const float* __restrict__ fcw, int layer) {
    __shared__ float At[64][68];
    __shared__ float Ws[32][128];
    int tid = threadIdx.x;
    int node0 = blockIdx.x * 64;
    if (blockIdx.x == 0 && tid < HA) { g_s2[tid] = 0.0; g_q2[tid] = 0.0; }
    for (int i = tid; i < 64 * 64; i += 256) {
        int n = i >> 6, k = i & 63;
        At[k][n] = d_atom[(node0 + n) * 64 + k];
    }
    int tx = tid & 15, ty = tid >> 4;
    for (int half = 0; half < 2; half++) {
        float acc[4][8];
#pragma unroll
        for (int r = 0; r < 4; r++)
#pragma unroll
            for (int c = 0; c < 8; c++) acc[r][c] = 0.f;
        const float* Wg = fcw + layer * FDIM * HO + half * 64 * HO;
        for (int chunk = 0; chunk < 2; chunk++) {
            __syncthreads();
            for (int i = tid; i < 32 * 128; i += 256) Ws[i >> 7][i & 127] = Wg[chunk * 4096 + i];
            __syncthreads();
#pragma unroll 8
            for (int k = 0; k < 32; k++) {
                float4 a = *(const float4*)&At[chunk * 32 + k][ty * 4];
                float4 w0 = *(const float4*)&Ws[k][tx * 8];
                float4 w1 = *(const float4*)&Ws[k][tx * 8 + 4];
                float av[4] = {a.x, a.y, a.z, a.w};
                float wv[8] = {w0.x, w0.y, w0.z, w0.w, w1.x, w1.y, w1.z, w1.w};
#pragma unroll
                for (int r = 0; r < 4; r++)
#pragma unroll
                    for (int c = 0; c < 8; c++) acc[r][c] += av[r] * wv[c];
            }
        }
        if (half == 0) {
#pragma unroll
            for (int r = 0; r < 4; r++) {
                float* op = d_P + (size_t)(node0 + ty * 4 + r) * HO + tx * 8;
                *(float4*)op = make_float4(acc[r][0], acc[r][1], acc[r][2], acc[r][3]);
                *(float4*)(op + 4) = make_float4(acc[r][4], acc[r][5], acc[r][6], acc[r][7]);
            }
        } else {
#pragma unroll
            for (int r = 0; r < 4; r++) {
                __half2* op = (__half2*)(d_Pnh + (size_t)(node0 + ty * 4 + r) * HO + tx * 8);
                op[0] = __floats2half2_rn(acc[r][0], acc[r][1]);
                op[1] = __floats2half2_rn(acc[r][2], acc[r][3]);
                op[2] = __floats2half2_rn(acc[r][4], acc[r][5]);
                op[3] = __floats2half2_rn(acc[r][6], acc[r][7]);
            }
        }
    }
}

// shared inner step: compute gated half2 pair for row m of this node
#define GATED_STEP(m)                                                                  \
    unsigned uw = __shfl_sync(0xffffffffu, p.w, m);                                    \
    unsigned u0 = __shfl_sync(0xffffffffu, p.x, m);                                    \
    unsigned u1 = __shfl_sync(0xffffffffu, p.y, m);                                    \
    unsigned u2 = __shfl_sync(0xffffffffu, p.z, m);                                    \
    int c = uw >> 16, nb = uw & 0xffff;                                                \
    __half2 g01 = u_to_h2(u0), g23 = u_to_h2(u1), g45 = u_to_h2(u2);                   \
    const __half* wp = Wsh + c * HO + lane * 4;                                        \
    uint2 w0 = *(const uint2*)(wp);                                                    \
    uint2 w1 = *(const uint2*)(wp + HO);                                               \
    uint2 w2 = *(const uint2*)(wp + 2 * HO);                                           \
    uint2 w3 = *(const uint2*)(wp + 3 * HO);                                           \
    uint2 w4 = *(const uint2*)(wp + 4 * HO);                                           \
    uint2 w5 = *(const uint2*)(wp + 5 * HO);                                           \
    __half2 accf = __hmul2(__half2half2(__low2half(g01)), u_to_h2(w0.x));              \
    __half2 accc = __hmul2(__half2half2(__low2half(g01)), u_to_h2(w0.y));              \
    accf = __hfma2(__half2half2(__high2half(g01)), u_to_h2(w1.x), accf);               \
    accc = __hfma2(__half2half2(__high2half(g01)), u_to_h2(w1.y), accc);               \
    accf = __hfma2(__half2half2(__low2half(g23)),  u_to_h2(w2.x), accf);               \
    accc = __hfma2(__half2half2(__low2half(g23)),  u_to_h2(w2.y), accc);               \
    accf = __hfma2(__half2half2(__high2half(g23)), u_to_h2(w3.x), accf);               \
    accc = __hfma2(__half2half2(__high2half(g23)), u_to_h2(w3.y), accc);               \
    accf = __hfma2(__half2half2(__low2half(g45)),  u_to_h2(w4.x), accf);               \
    accc = __hfma2(__half2half2(__low2half(g45)),  u_to_h2(w4.y), accc);               \
    accf = __hfma2(__half2half2(__high2half(g45)), u_to_h2(w5.x), accf);               \
    accc = __hfma2(__half2half2(__high2half(g45)), u_to_h2(w5.y), accc);               \
    const __half* pn = Pn + nb * HO + ch;                                              \
    accf = __hadd2(accf, *(const __half2*)(pn));                                       \
    accc = __hadd2(accc, *(const __half2*)(pn + 64));                                  \
    float2 vf = __half22float2(accf), vc = __half22float2(accc);                       \
    vf.x += base0.x; vf.y += base0.y; vc.x += base1.x; vc.y += base1.y;

// -------- pass 1: gated recompute for BN1 stats; 2 nodes per warp --------
__global__ void __launch_bounds__(256, 5) k_gstats(const float* __restrict__ fcb, int layer) {
    __shared__ __align__(16) __half Wsh[HB * HO];
    __shared__ float bs[HO], bq[HO];
    int tid = threadIdx.x, warp = tid >> 5, lane = tid & 31;
    const uint4* Wg = (const uint4*)(d_Wh + layer * HB * HO);
    for (int i = tid; i < HB * HO / 8; i += 256) ((uint4*)Wsh)[i] = Wg[i];
    if (tid < HO) { bs[tid] = 0.f; bq[tid] = 0.f; }
    __syncthreads();

    int ch = 2 * lane;
    float2 s0 = make_float2(0, 0), s1 = make_float2(0, 0);
    float2 q0 = make_float2(0, 0), q1 = make_float2(0, 0);
    for (int nn = 0; nn < 2; nn++) {
        int node = blockIdx.x * 16 + warp * 2 + nn;
        uint4 p = d_SGp[node * MM + lane];
        float2 base0 = *(const float2*)(d_P + node * HO + ch);
        float2 base1 = *(const float2*)(d_P + node * HO + 64 + ch);
        float2 bb0 = *(const float2*)(fcb + layer * HO + ch);
        float2 bb1 = *(const float2*)(fcb + layer * HO + 64 + ch);
        base0.x += bb0.x; base0.y += bb0.y; base1.x += bb1.x; base1.y += bb1.y;
        const __half* Pn = d_Pnh + (size_t)(node & ~(NN - 1)) * HO;
        for (int m = 0; m < MM; m++) {
            GATED_STEP(m)
            s0.x += vf.x; s0.y += vf.y; s1.x += vc.x; s1.y += vc.y;
            q0.x += vf.x * vf.x; q0.y += vf.y * vf.y;
            q1.x += vc.x * vc.x; q1.y += vc.y * vc.y;
        }
    }
    atomicAdd(&bs[ch], s0.x);      atomicAdd(&bs[ch + 1], s0.y);
    atomicAdd(&bs[ch + 64], s1.x); atomicAdd(&bs[ch + 65], s1.y);
    atomicAdd(&bq[ch], q0.x);      atomicAdd(&bq[ch + 1], q0.y);
    atomicAdd(&bq[ch + 64], q1.x); atomicAdd(&bq[ch + 65], q1.y);
    __syncthreads();
    if (tid < HO) { atomicAdd(&g_s1[tid], (double)bs[tid]); atomicAdd(&g_q1[tid], (double)bq[tid]); }
}

// -------- pass 2: recompute gated, BN1 apply, tanh-sigmoid*relu, sum_m; 2 nodes/warp --------
__global__ void __launch_bounds__(256, 5) k_greduce(const float* __restrict__ fcb,
                          const float* __restrict__ g1, const float* __restrict__ b1, int layer) {
    __shared__ __align__(16) __half Wsh[HB * HO];
    __shared__ float s_sc[HO], s_sh[HO];
    __shared__ float bs[HA], bq[HA];
    int tid = threadIdx.x, warp = tid >> 5, lane = tid & 31;
    const uint4* Wg = (const uint4*)(d_Wh + layer * HB * HO);
    for (int i = tid; i < HB * HO / 8; i += 256) ((uint4*)Wsh)[i] = Wg[i];
    if (tid < HO) {
        double inv = 1.0 / (double)NROWS;
        double mean = g_s1[tid] * inv;
        double var = g_q1[tid] * inv - mean * mean;
        float sc = g1[layer * HO + tid] * (float)(1.0 / sqrt(var + 1e-5));
        s_sc[tid] = sc;
        s_sh[tid] = b1[layer * HO + tid] - (float)mean * sc;
    }
    if (tid < HA) { bs[tid] = 0.f; bq[tid] = 0.f; }
    __syncthreads();

    int ch = 2 * lane;
    float sc0x = s_sc[ch], sc0y = s_sc[ch + 1], sh0x = s_sh[ch], sh0y = s_sh[ch + 1];
    float sc1x = s_sc[ch + 64], sc1y = s_sc[ch + 65], sh1x = s_sh[ch + 64], sh1y = s_sh[ch + 65];
    float sx = 0.f, sy = 0.f, qx = 0.f, qy = 0.f;
    for (int nn = 0; nn < 2; nn++) {
        int node = blockIdx.x * 16 + warp * 2 + nn;
        uint4 p = d_SGp[node * MM + lane];
        float2 base0 = *(const float2*)(d_P + node * HO + ch);
        float2 base1 = *(const float2*)(d_P + node * HO + 64 + ch);
        float2 bb0 = *(const float2*)(fcb + layer * HO + ch);
        float2 bb1 = *(const float2*)(fcb + layer * HO + 64 + ch);
        base0.x += bb0.x; base0.y += bb0.y; base1.x += bb1.x; base1.y += bb1.y;
        const __half* Pn = d_Pnh + (size_t)(node & ~(NN - 1)) * HO;
        float outx = 0.f, outy = 0.f;
        for (int m = 0; m < MM; m++) {
            GATED_STEP(m)
            float fx = vf.x * sc0x + sh0x;
            float fy = vf.y * sc0y + sh0y;
            float cx = vc.x * sc1x + sh1x;
            float cy = vc.y * sc1y + sh1y;
            outx += fmaxf(cx, 0.f) * sigt(fx);
            outy += fmaxf(cy, 0.f) * sigt(fy);
        }
        *(float2*)(d_summed + node * HA + ch) = make_float2(outx, outy);
        sx += outx; sy += outy; qx += outx * outx; qy += outy * outy;
    }
    atomicAdd(&bs[ch], sx);          atomicAdd(&bs[ch + 1], sy);
    atomicAdd(&bq[ch], qx);          atomicAdd(&bq[ch + 1], qy);
    __syncthreads();
    if (tid < HA) { atomicAdd(&g_s2[tid], (double)bs[tid]); atomicAdd(&g_q2[tid], (double)bq[tid]); }
}

// -------- residual + relu, with inline BN2 finalize --------
__global__ void k_update(const float* __restrict__ g2, const float* __restrict__ b2, int layer) {
    __shared__ float sc2[HA], sh2[HA];
    int tid = threadIdx.x;
    if (tid < HA) {
        double inv = 1.0 / (double)NNODES;
        double mean = g_s2[tid] * inv;
        double var = g_q2[tid] * inv - mean * mean;
        float sc = g2[layer * HA + tid] * (float)(1.0 / sqrt(var + 1e-5));
        sc2[tid] = sc;
        sh2[tid] = b2[layer * HA + tid] - (float)mean * sc;
    }
    if (blockIdx.x == 0 && tid < HO) { g_s1[tid] = 0.0; g_q1[tid] = 0.0; }
    __syncthreads();
    int i = blockIdx.x * 256 + tid;
    int ch = i & 63;
    float v = d_atom[i] + d_summed[i] * sc2[ch] + sh2[ch];
    d_atom[i] = fmaxf(v, 0.f);
}

// -------- pool, classify, softmax --------
__global__ void k_final(const float* __restrict__ clsw, const float* __restrict__ clsb,
                        float* __restrict__ out) {
    __shared__ float red[256];
    __shared__ float pooled[HA];
    __shared__ float lg[10], ex[10];
    __shared__ float mx, isum;
    int b = blockIdx.x, tid = threadIdx.x;
    int ch = tid & 63, seg = tid >> 6;
    const float* ab = d_atom + b * NN * HA;
    float acc = 0.f;
    for (int n = seg; n < NN; n += 4) acc += fmaxf(ab[n * HA + ch], 0.f);
    red[tid] = acc;
    __syncthreads();
    if (tid < HA) pooled[tid] = (red[tid] + red[tid + 64] + red[tid + 128] + red[tid + 192]) * (1.0f / (float)NN);
    __syncthreads();
    if (tid < 10) {
        float a = clsb[tid];
#pragma unroll
        for (int k = 0; k < HA; k++) a += pooled[k] * clsw[k * 10 + tid];
        lg[tid] = a;
    }
    __syncthreads();
    if (tid == 0) { float m = lg[0]; for (int i = 1; i < 10; i++) m = fmaxf(m, lg[i]); mx = m; }
    __syncthreads();
    if (tid < 10) ex[tid] = expf(lg[tid] - mx);
    __syncthreads();
    if (tid == 0) { float s = 0.f; for (int i = 0; i < 10; i++) s += ex[i]; isum = 1.f / s; }
    __syncthreads();
    if (tid < 10) out[b * 10 + tid] = ex[tid] * isum;
}

extern "C" void kernel_launch(void* const* d_in, const int* in_sizes, int n_in,
                              void* d_out, int out_size) {
    const float* dist = (const float*)d_in[0];
    const int*   adj  = (const int*)d_in[1];
    const float* emb  = (const float*)d_in[2];
    const float* fcw  = (const float*)d_in[3];
    const float* fcb  = (const float*)d_in[4];
    const float* b1g  = (const float*)d_in[5];
    const float* b1b  = (const float*)d_in[6];
    const float* b2g  = (const float*)d_in[7];
    const float* b2b  = (const float*)d_in[8];
    const float* clsw = (const float*)d_in[9];
    const float* clsb = (const float*)d_in[10];
    float* out = (float*)d_out;

    k_init<<<NNODES * HA / 256, 256>>>(emb);
    k_wprep<<<202, 256>>>(fcw);
    k_gauss<<<NROWS / 256, 256>>>(dist, adj);
    for (int l = 0; l < 4; l++) {
        k_proj<<<NNODES / 64, 256>>>(fcw, l);
        k_gstats<<<NNODES / 16, 256>>>(fcb, l);
        k_greduce<<<NNODES / 16, 256>>>(fcb, b1g, b1b, l);
        k_update<<<NNODES * HA / 256, 256>>>(b2g, b2b, l);
    }
    k_final<<<BB, 256>>>(clsw, clsb, out);
}